// round 8
// baseline (speedup 1.0000x reference)
#include <cuda_runtime.h>
#include <cuda_bf16.h>
#include <cstdint>

// Problem constants
#define NN 200000
#define FF 602
#define FP 608          // padded K (mult of 16)
#define DD 128
#define HH 256
#define CC 41
#define BB 1024
#define SS1 25
#define SS2 10
#define M1 (BB*SS2)     // 10240

// ---------------- scratch (device globals; no allocation allowed) -------------
__device__ __align__(16) float g_fh0[(size_t)M1*FP];       // features[hop0], padded
__device__ __align__(16) float g_neigh1[(size_t)M1*FP];    // mean over hop1 neighbors
__device__ __align__(16) float g_selfx[(size_t)BB*FP];     // features[x]
__device__ __align__(16) float g_mean_fh0[(size_t)BB*FP];  // mean over S2 of fh0
__device__ __align__(16) float g_featmap1[(size_t)M1*2*HH];
__device__ __align__(16) float g_featmap0[(size_t)BB*2*HH];
__device__ __align__(16) float g_x1[(size_t)BB*2*HH];
__device__ __align__(16) float g_out512[(size_t)BB*2*HH];
__device__ __align__(16) float g_wpad[4*(size_t)HH*FP];    // w1a_self, w1a_neigh, w1b_self, w1b_neigh padded

// ---------------- pad weights [256,602] -> [256,608] --------------------------
__global__ void pad_w_kernel(const float* __restrict__ w0, const float* __restrict__ w1,
                             const float* __restrict__ w2, const float* __restrict__ w3) {
    int z = blockIdx.y;
    const float* src = (z == 0) ? w0 : (z == 1) ? w1 : (z == 2) ? w2 : w3;
    float* dst = g_wpad + (size_t)z * HH * FP;
    int idx = blockIdx.x * 256 + threadIdx.x;
    if (idx < HH * FP) {
        int r = idx / FP, c = idx % FP;
        dst[idx] = (c < FF) ? src[r * FF + c] : 0.f;
    }
}

// ---------------- hop0 index + hop1 gather + neighbor mean + fh0 copy ---------
// One CTA (256 threads) per (b,s) row. Feature rows are 602 floats = 8B-aligned
// (602*4 % 16 == 8), so float2 is the widest safe vector.
__global__ __launch_bounds__(256)
void gather_hop_kernel(const float* __restrict__ features,
                       const int* __restrict__ adj,
                       const int* __restrict__ x,
                       const int* __restrict__ perm0,
                       const int* __restrict__ perm1) {
    int row = blockIdx.x;          // 0..M1-1
    int tid = threadIdx.x;
    __shared__ int nb[SS1];
    __shared__ int hs;
    if (tid == 0) {
        int b = row / SS2, s = row % SS2;
        hs = adj[(size_t)x[b] * DD + perm0[s]];
    }
    __syncthreads();
    int h = hs;
    if (tid < SS1) nb[tid] = adj[(size_t)h * DD + perm1[tid]];
    __syncthreads();

    const float2* fr = (const float2*)(features + (size_t)h * FF);
    float2* fh0r = (float2*)(g_fh0 + (size_t)row * FP);
    float2* n1r  = (float2*)(g_neigh1 + (size_t)row * FP);

    // 602 floats = 301 float2; padded region [301..304) zeroed.
    for (int f = tid; f < FP / 2; f += 256) {
        float2 v = make_float2(0.f, 0.f);
        float ax = 0.f, ay = 0.f;
        if (f < FF / 2) {
            v = __ldg(fr + f);
#pragma unroll
            for (int i = 0; i < SS1; i++) {
                float2 t = __ldg((const float2*)(features + (size_t)nb[i] * FF) + f);
                ax += t.x; ay += t.y;
            }
        }
        fh0r[f] = v;
        n1r[f]  = make_float2(ax * (1.f / SS1), ay * (1.f / SS1));
    }
}

// ---------------- seed gather + S2-mean of fh0 --------------------------------
__global__ __launch_bounds__(256)
void gather_seed_kernel(const float* __restrict__ features,
                        const int* __restrict__ x) {
    int b = blockIdx.x;
    int tid = threadIdx.x;
    int xb = x[b];
    const float2* fr = (const float2*)(features + (size_t)xb * FF);
    float2* sx = (float2*)(g_selfx + (size_t)b * FP);
    float2* mf = (float2*)(g_mean_fh0 + (size_t)b * FP);
    for (int f = tid; f < FP / 2; f += 256) {
        float2 v = make_float2(0.f, 0.f);
        if (f < FF / 2) v = __ldg(fr + f);
        sx[f] = v;
        float ax = 0.f, ay = 0.f;
#pragma unroll
        for (int s = 0; s < SS2; s++) {
            float2 t = *((const float2*)(g_fh0 + (size_t)(b * SS2 + s) * FP) + f);
            ax += t.x; ay += t.y;
        }
        mf[f] = make_float2(ax * (1.f / SS2), ay * (1.f / SS2));
    }
}

// ---------------- dual-half tiled SGEMM + bias + optional relu ----------------
// BM=128 x BN=64 tile, 128 threads (8x8 per thread), smem double-buffered.
// 4 CTAs/SM (24 KB smem, <=128 regs) -> GEMM1 grid 640 CTAs ~ 1.08 waves.
// C[m, z*256 + bx*64 + n] with ldc = 512.
// A row-major [M,K], W row-major [256,K]; K % 16 == 0; M % 128 == 0.
#define BM 128
#define BN 64
#define BK 16
__global__ __launch_bounds__(128, 4)
void sgemm_dual(const float* __restrict__ A0, const float* __restrict__ W0, const float* __restrict__ bias0,
                const float* __restrict__ A1, const float* __restrict__ W1, const float* __restrict__ bias1,
                float* __restrict__ C, int M, int K, int relu) {
    const int z = blockIdx.z;
    const float* A = z ? A1 : A0;
    const float* W = z ? W1 : W0;
    const float* bias = z ? bias1 : bias0;
    const int rowBase = blockIdx.y * BM;
    const int colBase = blockIdx.x * BN;   // within the 256-wide half
    const int tid = threadIdx.x;           // 0..127

    __shared__ float As[2][BK][BM];
    __shared__ float Bs[2][BK][BN];

    // A loader: one thread per row, full 16-float k-slab (4 float4)
    const float* Ag = A + (size_t)(rowBase + tid) * K;
    // B loader: row = tid/2, 8 floats (2 float4) at col (tid&1)*8
    const int brow = tid >> 1;
    const int bcol = (tid & 1) * 8;
    const float* Wg = W + (size_t)(colBase + brow) * K + bcol;

    const int tx = tid & 7;    // 8 col-groups of 8
    const int ty = tid >> 3;   // 16 row-groups of 8

    float acc[8][8];
#pragma unroll
    for (int i = 0; i < 8; i++)
#pragma unroll
        for (int j = 0; j < 8; j++) acc[i][j] = 0.f;

    // prologue: fill smem buffer 0
    {
        float4 a0v = *(const float4*)(Ag + 0);
        float4 a1v = *(const float4*)(Ag + 4);
        float4 a2v = *(const float4*)(Ag + 8);
        float4 a3v = *(const float4*)(Ag + 12);
        float4 w0v = *(const float4*)(Wg + 0);
        float4 w1v = *(const float4*)(Wg + 4);
        As[0][ 0][tid] = a0v.x; As[0][ 1][tid] = a0v.y; As[0][ 2][tid] = a0v.z; As[0][ 3][tid] = a0v.w;
        As[0][ 4][tid] = a1v.x; As[0][ 5][tid] = a1v.y; As[0][ 6][tid] = a1v.z; As[0][ 7][tid] = a1v.w;
        As[0][ 8][tid] = a2v.x; As[0][ 9][tid] = a2v.y; As[0][10][tid] = a2v.z; As[0][11][tid] = a2v.w;
        As[0][12][tid] = a3v.x; As[0][13][tid] = a3v.y; As[0][14][tid] = a3v.z; As[0][15][tid] = a3v.w;
        Bs[0][bcol + 0][brow] = w0v.x; Bs[0][bcol + 1][brow] = w0v.y;
        Bs[0][bcol + 2][brow] = w0v.z; Bs[0][bcol + 3][brow] = w0v.w;
        Bs[0][bcol + 4][brow] = w1v.x; Bs[0][bcol + 5][brow] = w1v.y;
        Bs[0][bcol + 6][brow] = w1v.z; Bs[0][bcol + 7][brow] = w1v.w;
    }
    __syncthreads();

    int buf = 0;
    for (int kt = BK; kt < K; kt += BK) {
        // prefetch next k-tile to registers
        float4 a0v = *(const float4*)(Ag + kt + 0);
        float4 a1v = *(const float4*)(Ag + kt + 4);
        float4 a2v = *(const float4*)(Ag + kt + 8);
        float4 a3v = *(const float4*)(Ag + kt + 12);
        float4 w0v = *(const float4*)(Wg + kt + 0);
        float4 w1v = *(const float4*)(Wg + kt + 4);

        // compute on current buffer
#pragma unroll
        for (int kk = 0; kk < BK; kk++) {
            float a[8], bfr[8];
#pragma unroll
            for (int i = 0; i < 8; i++) a[i] = As[buf][kk][ty * 8 + i];
#pragma unroll
            for (int j = 0; j < 8; j++) bfr[j] = Bs[buf][kk][tx * 8 + j];
#pragma unroll
            for (int i = 0; i < 8; i++)
#pragma unroll
                for (int j = 0; j < 8; j++)
                    acc[i][j] += a[i] * bfr[j];
        }

        // store prefetched k-tile into the other smem buffer
        buf ^= 1;
        As[buf][ 0][tid] = a0v.x; As[buf][ 1][tid] = a0v.y; As[buf][ 2][tid] = a0v.z; As[buf][ 3][tid] = a0v.w;
        As[buf][ 4][tid] = a1v.x; As[buf][ 5][tid] = a1v.y; As[buf][ 6][tid] = a1v.z; As[buf][ 7][tid] = a1v.w;
        As[buf][ 8][tid] = a2v.x; As[buf][ 9][tid] = a2v.y; As[buf][10][tid] = a2v.z; As[buf][11][tid] = a2v.w;
        As[buf][12][tid] = a3v.x; As[buf][13][tid] = a3v.y; As[buf][14][tid] = a3v.z; As[buf][15][tid] = a3v.w;
        Bs[buf][bcol + 0][brow] = w0v.x; Bs[buf][bcol + 1][brow] = w0v.y;
        Bs[buf][bcol + 2][brow] = w0v.z; Bs[buf][bcol + 3][brow] = w0v.w;
        Bs[buf][bcol + 4][brow] = w1v.x; Bs[buf][bcol + 5][brow] = w1v.y;
        Bs[buf][bcol + 6][brow] = w1v.z; Bs[buf][bcol + 7][brow] = w1v.w;
        __syncthreads();
    }

    // epilogue: compute last buffer
#pragma unroll
    for (int kk = 0; kk < BK; kk++) {
        float a[8], bfr[8];
#pragma unroll
        for (int i = 0; i < 8; i++) a[i] = As[buf][kk][ty * 8 + i];
#pragma unroll
        for (int j = 0; j < 8; j++) bfr[j] = Bs[buf][kk][tx * 8 + j];
#pragma unroll
        for (int i = 0; i < 8; i++)
#pragma unroll
            for (int j = 0; j < 8; j++)
                acc[i][j] += a[i] * bfr[j];
    }

    const int gcolBase = z * 256 + colBase + tx * 8;
#pragma unroll
    for (int i = 0; i < 8; i++) {
        int r = rowBase + ty * 8 + i;
        float* Crow = C + (size_t)r * 512 + gcolBase;
#pragma unroll
        for (int j = 0; j < 8; j++) {
            float v = acc[i][j] + bias[colBase + tx * 8 + j];
            if (relu) v = fmaxf(v, 0.f);
            Crow[j] = v;
        }
    }
}

// ---------------- x1 = mean over S2 of featmap1 -------------------------------
__global__ void reduce_x1_kernel() {
    int b = blockIdx.x;
    int h = threadIdx.x;   // 512
    float acc = 0.f;
#pragma unroll
    for (int s = 0; s < SS2; s++)
        acc += g_featmap1[(size_t)(b * SS2 + s) * 512 + h];
    g_x1[(size_t)b * 512 + h] = acc * (1.f / SS2);
}

// ---------------- layernorm + classifier --------------------------------------
__device__ __forceinline__ float blockSum512(float v, float* red) {
    int tid = threadIdx.x, lane = tid & 31, w = tid >> 5;
#pragma unroll
    for (int o = 16; o > 0; o >>= 1) v += __shfl_xor_sync(0xffffffffu, v, o);
    if (lane == 0) red[w] = v;
    __syncthreads();
    float t = (tid < 16) ? red[tid] : 0.f;
    if (w == 0) {
#pragma unroll
        for (int o = 16; o > 0; o >>= 1) t += __shfl_xor_sync(0xffffffffu, t, o);
        if (lane == 0) red[16] = t;
    }
    __syncthreads();
    float r = red[16];
    __syncthreads();
    return r;
}

__global__ __launch_bounds__(512)
void ln_cls_kernel(const float* __restrict__ ln_g, const float* __restrict__ ln_b,
                   const float* __restrict__ w_cls, const float* __restrict__ b_cls,
                   float* __restrict__ out) {
    int b = blockIdx.x;
    int tid = threadIdx.x;   // 512
    __shared__ float row[512];
    __shared__ float red[17];

    float v = g_out512[(size_t)b * 512 + tid];
    float mean = blockSum512(v, red) * (1.f / 512.f);
    float d = v - mean;
    float var = blockSum512(d * d, red) * (1.f / 512.f);
    float inv = rsqrtf(var + 1e-12f);
    row[tid] = d * inv * ln_g[tid] + ln_b[tid];
    __syncthreads();

    int lane = tid & 31, w = tid >> 5;   // 16 warps
    for (int c = w; c < CC; c += 16) {
        const float* wr = w_cls + (size_t)c * 512;
        float acc = 0.f;
#pragma unroll 4
        for (int e = lane; e < 512; e += 32)
            acc += row[e] * __ldg(wr + e);
#pragma unroll
        for (int o = 16; o > 0; o >>= 1) acc += __shfl_xor_sync(0xffffffffu, acc, o);
        if (lane == 0) out[(size_t)b * CC + c] = acc + b_cls[c];
    }
}

// ---------------- launch ------------------------------------------------------
extern "C" void kernel_launch(void* const* d_in, const int* in_sizes, int n_in,
                              void* d_out, int out_size) {
    const int*   x         = (const int*)  d_in[0];
    const int*   adj       = (const int*)  d_in[1];
    const int*   perm0     = (const int*)  d_in[2];
    const int*   perm1     = (const int*)  d_in[3];
    const float* features  = (const float*)d_in[4];
    const float* w1a_self  = (const float*)d_in[5];
    const float* b1a_self  = (const float*)d_in[6];
    const float* w1a_neigh = (const float*)d_in[7];
    const float* b1a_neigh = (const float*)d_in[8];
    const float* w1b_self  = (const float*)d_in[9];
    const float* b1b_self  = (const float*)d_in[10];
    const float* w1b_neigh = (const float*)d_in[11];
    const float* b1b_neigh = (const float*)d_in[12];
    const float* w2_self   = (const float*)d_in[13];
    const float* b2_self   = (const float*)d_in[14];
    const float* w2_neigh  = (const float*)d_in[15];
    const float* b2_neigh  = (const float*)d_in[16];
    const float* ln_g      = (const float*)d_in[17];
    const float* ln_b      = (const float*)d_in[18];
    const float* w_cls     = (const float*)d_in[19];
    const float* b_cls     = (const float*)d_in[20];
    float* out = (float*)d_out;

    // resolve scratch addresses (host-side query, no allocation)
    float *fh0, *neigh1, *selfx, *mean_fh0, *fm1, *fm0, *x1v, *out512, *wpad;
    cudaGetSymbolAddress((void**)&fh0,      g_fh0);
    cudaGetSymbolAddress((void**)&neigh1,   g_neigh1);
    cudaGetSymbolAddress((void**)&selfx,    g_selfx);
    cudaGetSymbolAddress((void**)&mean_fh0, g_mean_fh0);
    cudaGetSymbolAddress((void**)&fm1,      g_featmap1);
    cudaGetSymbolAddress((void**)&fm0,      g_featmap0);
    cudaGetSymbolAddress((void**)&x1v,      g_x1);
    cudaGetSymbolAddress((void**)&out512,   g_out512);
    cudaGetSymbolAddress((void**)&wpad,     g_wpad);

    // 1) pad the four layer-1 weight matrices
    pad_w_kernel<<<dim3((HH * FP + 255) / 256, 4), 256>>>(w1a_self, w1a_neigh, w1b_self, w1b_neigh);
    // 2) hop0 index + hop1 gather + neighbor mean + fh0 materialize
    gather_hop_kernel<<<M1, 256>>>(features, adj, x, perm0, perm1);
    // 3) seed gather + hop0 mean
    gather_seed_kernel<<<BB, 256>>>(features, x);
    // 4) featmap1 = relu([fh0 @ w1b_self^T | neigh1 @ w1b_neigh^T] + bias)
    sgemm_dual<<<dim3(256 / BN, M1 / BM, 2), 128>>>(
        fh0,    wpad + (size_t)2 * HH * FP, b1b_self,
        neigh1, wpad + (size_t)3 * HH * FP, b1b_neigh,
        fm1, M1, FP, 1);
    // 5) featmap0 = relu([selfx @ w1a_self^T | mean_fh0 @ w1a_neigh^T] + bias)
    sgemm_dual<<<dim3(256 / BN, BB / BM, 2), 128>>>(
        selfx,    wpad + (size_t)0 * HH * FP, b1a_self,
        mean_fh0, wpad + (size_t)1 * HH * FP, b1a_neigh,
        fm0, BB, FP, 1);
    // 6) x1 = mean over S2 of featmap1
    reduce_x1_kernel<<<BB, 512>>>();
    // 7) out512 = [featmap0 @ w2_self^T | x1 @ w2_neigh^T] + bias (no relu)
    sgemm_dual<<<dim3(256 / BN, BB / BM, 2), 128>>>(
        fm0, w2_self,  b2_self,
        x1v, w2_neigh, b2_neigh,
        out512, BB, 512, 0);
    // 8) layernorm + classifier
    ln_cls_kernel<<<BB, 512>>>(ln_g, ln_b, w_cls, b_cls, out);
}

// round 9
// speedup vs baseline: 1.5168x; 1.5168x over previous
#include <cuda_runtime.h>
#include <cuda_bf16.h>
#include <mma.h>
#include <cstdint>

using namespace nvcuda;

// Problem constants
#define NN 200000
#define FF 602
#define FP 608          // padded K (mult of 16)
#define DD 128
#define HH 256
#define CC 41
#define BB 1024
#define SS1 25
#define SS2 10
#define M1 (BB*SS2)     // 10240

// ---------------- scratch (device globals; no allocation allowed) -------------
__device__ __align__(16) float g_fh0[(size_t)M1*FP];       // features[hop0], padded
__device__ __align__(16) float g_neigh1[(size_t)M1*FP];    // mean over hop1 neighbors
__device__ __align__(16) float g_selfx[(size_t)BB*FP];     // features[x]
__device__ __align__(16) float g_mean_fh0[(size_t)BB*FP];  // mean over S2 of fh0
__device__ __align__(16) float g_featmap1[(size_t)M1*2*HH];  // raw GEMM out (bias/relu folded into reduce)
__device__ __align__(16) float g_featmap0[(size_t)BB*2*HH];
__device__ __align__(16) float g_x1[(size_t)BB*2*HH];
__device__ __align__(16) float g_out512[(size_t)BB*2*HH];
__device__ __align__(16) float g_wpad[4*(size_t)HH*FP];    // w1a_self, w1a_neigh, w1b_self, w1b_neigh padded

// ---------------- pad weights [256,602] -> [256,608] --------------------------
__global__ void pad_w_kernel(const float* __restrict__ w0, const float* __restrict__ w1,
                             const float* __restrict__ w2, const float* __restrict__ w3) {
    int z = blockIdx.y;
    const float* src = (z == 0) ? w0 : (z == 1) ? w1 : (z == 2) ? w2 : w3;
    float* dst = g_wpad + (size_t)z * HH * FP;
    int idx = blockIdx.x * 256 + threadIdx.x;
    if (idx < HH * FP) {
        int r = idx / FP, c = idx % FP;
        dst[idx] = (c < FF) ? src[r * FF + c] : 0.f;
    }
}

// ---------------- hop0 index + hop1 gather + neighbor mean + fh0 copy ---------
__global__ __launch_bounds__(256)
void gather_hop_kernel(const float* __restrict__ features,
                       const int* __restrict__ adj,
                       const int* __restrict__ x,
                       const int* __restrict__ perm0,
                       const int* __restrict__ perm1) {
    int row = blockIdx.x;          // 0..M1-1
    int tid = threadIdx.x;
    __shared__ int nb[SS1];
    __shared__ int hs;
    if (tid == 0) {
        int b = row / SS2, s = row % SS2;
        hs = adj[(size_t)x[b] * DD + perm0[s]];
    }
    __syncthreads();
    int h = hs;
    if (tid < SS1) nb[tid] = adj[(size_t)h * DD + perm1[tid]];
    __syncthreads();

    const float2* fr = (const float2*)(features + (size_t)h * FF);
    float2* fh0r = (float2*)(g_fh0 + (size_t)row * FP);
    float2* n1r  = (float2*)(g_neigh1 + (size_t)row * FP);

    for (int f = tid; f < FP / 2; f += 256) {
        float2 v = make_float2(0.f, 0.f);
        float ax = 0.f, ay = 0.f;
        if (f < FF / 2) {
            v = __ldg(fr + f);
#pragma unroll
            for (int i = 0; i < SS1; i++) {
                float2 t = __ldg((const float2*)(features + (size_t)nb[i] * FF) + f);
                ax += t.x; ay += t.y;
            }
        }
        fh0r[f] = v;
        n1r[f]  = make_float2(ax * (1.f / SS1), ay * (1.f / SS1));
    }
}

// ---------------- seed gather + S2-mean of fh0 --------------------------------
__global__ __launch_bounds__(256)
void gather_seed_kernel(const float* __restrict__ features,
                        const int* __restrict__ x) {
    int b = blockIdx.x;
    int tid = threadIdx.x;
    int xb = x[b];
    const float2* fr = (const float2*)(features + (size_t)xb * FF);
    float2* sx = (float2*)(g_selfx + (size_t)b * FP);
    float2* mf = (float2*)(g_mean_fh0 + (size_t)b * FP);
    for (int f = tid; f < FP / 2; f += 256) {
        float2 v = make_float2(0.f, 0.f);
        if (f < FF / 2) v = __ldg(fr + f);
        sx[f] = v;
        float ax = 0.f, ay = 0.f;
#pragma unroll
        for (int s = 0; s < SS2; s++) {
            float2 t = *((const float2*)(g_fh0 + (size_t)(b * SS2 + s) * FP) + f);
            ax += t.x; ay += t.y;
        }
        mf[f] = make_float2(ax * (1.f / SS2), ay * (1.f / SS2));
    }
}

// ---------------- tf32 wmma dual-half GEMM (pure C = A @ W^T) ------------------
// BM=128 x BN=64, 4 warps (2x2), wmma 16x16x8 tf32, 2-stage cp.async pipeline.
// C[m, z*256 + bx*64 + n], ldc=512. A [M,K] rm, W [256,K] rm, K%16==0, M%128==0.
#define BM 128
#define BN 64
#define BK 16
#define LDA 20   // padded smem stride (mult of 4 for wmma)

__device__ __forceinline__ void cpasync16(uint32_t s, const void* g) {
    asm volatile("cp.async.cg.shared.global [%0], [%1], 16;" :: "r"(s), "l"(g));
}
__device__ __forceinline__ void cpasync_commit() {
    asm volatile("cp.async.commit_group;");
}

__global__ __launch_bounds__(128, 4)
void wmma_gemm_dual(const float* __restrict__ A0, const float* __restrict__ W0,
                    const float* __restrict__ A1, const float* __restrict__ W1,
                    float* __restrict__ C, int M, int K) {
    const int z = blockIdx.z;
    const float* A = z ? A1 : A0;
    const float* W = z ? W1 : W0;
    const int rowBase = blockIdx.y * BM;
    const int colBase = blockIdx.x * BN;   // within the 256-wide half
    const int tid = threadIdx.x;           // 0..127
    const int wid = tid >> 5;
    const int wm = wid & 1;                // warp m index (0..1) -> 64 rows
    const int wn = wid >> 1;               // warp n index (0..1) -> 32 cols

    __shared__ float As[2][BM][LDA];
    __shared__ float Bs[2][BN][LDA];

    // loader: A = 512 float4 (4/thread), B = 256 float4 (2/thread)
    const int am[4]  = { (tid + 0) >> 2, (tid + 128) >> 2, (tid + 256) >> 2, (tid + 384) >> 2 };
    const int akq    = (tid & 3) * 4;
    const int bn0    = (tid + 0) >> 2, bn1 = (tid + 128) >> 2;

    uint32_t sA0 = (uint32_t)__cvta_generic_to_shared(&As[0][0][0]);
    uint32_t sB0 = (uint32_t)__cvta_generic_to_shared(&Bs[0][0][0]);
    const uint32_t bufA = BM * LDA * 4, bufB = BN * LDA * 4;

    const int NT = K / BK;

    // prologue: issue tiles 0 and 1
#pragma unroll
    for (int st = 0; st < 2; st++) {
        int kt = st * BK;
        uint32_t sa = sA0 + st * bufA, sb = sB0 + st * bufB;
#pragma unroll
        for (int c = 0; c < 4; c++)
            cpasync16(sa + (am[c] * LDA + akq) * 4, A + (size_t)(rowBase + am[c]) * K + kt + akq);
        cpasync16(sb + (bn0 * LDA + akq) * 4, W + (size_t)(colBase + bn0) * K + kt + akq);
        cpasync16(sb + (bn1 * LDA + akq) * 4, W + (size_t)(colBase + bn1) * K + kt + akq);
        cpasync_commit();
    }

    wmma::fragment<wmma::accumulator, 16, 16, 8, float> acc[4][2];
#pragma unroll
    for (int i = 0; i < 4; i++)
#pragma unroll
        for (int j = 0; j < 2; j++) wmma::fill_fragment(acc[i][j], 0.f);

    int buf = 0;
    for (int t = 0; t < NT; t++) {
        if (t < NT - 1) asm volatile("cp.async.wait_group 1;");
        else            asm volatile("cp.async.wait_group 0;");
        __syncthreads();

        // compute on buf
#pragma unroll
        for (int ks = 0; ks < BK; ks += 8) {
            wmma::fragment<wmma::matrix_a, 16, 16, 8, wmma::precision::tf32, wmma::row_major> af[4];
            wmma::fragment<wmma::matrix_b, 16, 16, 8, wmma::precision::tf32, wmma::col_major> bf[2];
#pragma unroll
            for (int i = 0; i < 4; i++) {
                wmma::load_matrix_sync(af[i], &As[buf][wm * 64 + i * 16][ks], LDA);
#pragma unroll
                for (int e = 0; e < af[i].num_elements; e++)
                    af[i].x[e] = wmma::__float_to_tf32(af[i].x[e]);
            }
#pragma unroll
            for (int j = 0; j < 2; j++) {
                wmma::load_matrix_sync(bf[j], &Bs[buf][wn * 32 + j * 16][ks], LDA);
#pragma unroll
                for (int e = 0; e < bf[j].num_elements; e++)
                    bf[j].x[e] = wmma::__float_to_tf32(bf[j].x[e]);
            }
#pragma unroll
            for (int i = 0; i < 4; i++)
#pragma unroll
                for (int j = 0; j < 2; j++)
                    wmma::mma_sync(acc[i][j], af[i], bf[j], acc[i][j]);
        }
        __syncthreads();   // everyone done reading buf before overwrite

        if (t + 2 < NT) {
            int kt = (t + 2) * BK;
            uint32_t sa = sA0 + buf * bufA, sb = sB0 + buf * bufB;
#pragma unroll
            for (int c = 0; c < 4; c++)
                cpasync16(sa + (am[c] * LDA + akq) * 4, A + (size_t)(rowBase + am[c]) * K + kt + akq);
            cpasync16(sb + (bn0 * LDA + akq) * 4, W + (size_t)(colBase + bn0) * K + kt + akq);
            cpasync16(sb + (bn1 * LDA + akq) * 4, W + (size_t)(colBase + bn1) * K + kt + akq);
            cpasync_commit();
        }
        buf ^= 1;
    }

    // store raw accumulators (bias/activation folded into consumers)
    const int gcol = z * 256 + colBase + wn * 32;
#pragma unroll
    for (int i = 0; i < 4; i++) {
        int r = rowBase + wm * 64 + i * 16;
#pragma unroll
        for (int j = 0; j < 2; j++)
            wmma::store_matrix_sync(C + (size_t)r * 512 + gcol + j * 16, acc[i][j], 512, wmma::mem_row_major);
    }
}

// ---------------- bias+relu in place (featmap0) --------------------------------
__global__ void bias_relu_kernel(float* __restrict__ buf,
                                 const float* __restrict__ b_self,
                                 const float* __restrict__ b_neigh) {
    int r = blockIdx.x;
    int c = threadIdx.x;   // 512
    float bias = (c < HH) ? b_self[c] : b_neigh[c - HH];
    float v = buf[(size_t)r * 512 + c] + bias;
    buf[(size_t)r * 512 + c] = fmaxf(v, 0.f);
}

// ---------------- x1 = mean over S2 of relu(featmap1 + bias) -------------------
__global__ void reduce_x1_kernel(const float* __restrict__ b_self,
                                 const float* __restrict__ b_neigh) {
    int b = blockIdx.x;
    int h = threadIdx.x;   // 512
    float bias = (h < HH) ? b_self[h] : b_neigh[h - HH];
    float acc = 0.f;
#pragma unroll
    for (int s = 0; s < SS2; s++)
        acc += fmaxf(g_featmap1[(size_t)(b * SS2 + s) * 512 + h] + bias, 0.f);
    g_x1[(size_t)b * 512 + h] = acc * (1.f / SS2);
}

// ---------------- layernorm + classifier (layer-2 bias folded in) -------------
__device__ __forceinline__ float blockSum512(float v, float* red) {
    int tid = threadIdx.x, lane = tid & 31, w = tid >> 5;
#pragma unroll
    for (int o = 16; o > 0; o >>= 1) v += __shfl_xor_sync(0xffffffffu, v, o);
    if (lane == 0) red[w] = v;
    __syncthreads();
    float t = (tid < 16) ? red[tid] : 0.f;
    if (w == 0) {
#pragma unroll
        for (int o = 16; o > 0; o >>= 1) t += __shfl_xor_sync(0xffffffffu, t, o);
        if (lane == 0) red[16] = t;
    }
    __syncthreads();
    float r = red[16];
    __syncthreads();
    return r;
}

__global__ __launch_bounds__(512)
void ln_cls_kernel(const float* __restrict__ b2_self, const float* __restrict__ b2_neigh,
                   const float* __restrict__ ln_g, const float* __restrict__ ln_b,
                   const float* __restrict__ w_cls, const float* __restrict__ b_cls,
                   float* __restrict__ out) {
    int b = blockIdx.x;
    int tid = threadIdx.x;   // 512
    __shared__ float row[512];
    __shared__ float red[17];

    float bias = (tid < HH) ? b2_self[tid] : b2_neigh[tid - HH];
    float v = g_out512[(size_t)b * 512 + tid] + bias;
    float mean = blockSum512(v, red) * (1.f / 512.f);
    float d = v - mean;
    float var = blockSum512(d * d, red) * (1.f / 512.f);
    float inv = rsqrtf(var + 1e-12f);
    row[tid] = d * inv * ln_g[tid] + ln_b[tid];
    __syncthreads();

    int lane = tid & 31, w = tid >> 5;   // 16 warps
    for (int c = w; c < CC; c += 16) {
        const float* wr = w_cls + (size_t)c * 512;
        float acc = 0.f;
#pragma unroll 4
        for (int e = lane; e < 512; e += 32)
            acc += row[e] * __ldg(wr + e);
#pragma unroll
        for (int o = 16; o > 0; o >>= 1) acc += __shfl_xor_sync(0xffffffffu, acc, o);
        if (lane == 0) out[(size_t)b * CC + c] = acc + b_cls[c];
    }
}

// ---------------- launch ------------------------------------------------------
extern "C" void kernel_launch(void* const* d_in, const int* in_sizes, int n_in,
                              void* d_out, int out_size) {
    const int*   x         = (const int*)  d_in[0];
    const int*   adj       = (const int*)  d_in[1];
    const int*   perm0     = (const int*)  d_in[2];
    const int*   perm1     = (const int*)  d_in[3];
    const float* features  = (const float*)d_in[4];
    const float* w1a_self  = (const float*)d_in[5];
    const float* b1a_self  = (const float*)d_in[6];
    const float* w1a_neigh = (const float*)d_in[7];
    const float* b1a_neigh = (const float*)d_in[8];
    const float* w1b_self  = (const float*)d_in[9];
    const float* b1b_self  = (const float*)d_in[10];
    const float* w1b_neigh = (const float*)d_in[11];
    const float* b1b_neigh = (const float*)d_in[12];
    const float* w2_self   = (const float*)d_in[13];
    const float* b2_self   = (const float*)d_in[14];
    const float* w2_neigh  = (const float*)d_in[15];
    const float* b2_neigh  = (const float*)d_in[16];
    const float* ln_g      = (const float*)d_in[17];
    const float* ln_b      = (const float*)d_in[18];
    const float* w_cls     = (const float*)d_in[19];
    const float* b_cls     = (const float*)d_in[20];
    float* out = (float*)d_out;

    // resolve scratch addresses (host-side query, no allocation)
    float *fh0, *neigh1, *selfx, *mean_fh0, *fm1, *fm0, *x1v, *out512, *wpad;
    cudaGetSymbolAddress((void**)&fh0,      g_fh0);
    cudaGetSymbolAddress((void**)&neigh1,   g_neigh1);
    cudaGetSymbolAddress((void**)&selfx,    g_selfx);
    cudaGetSymbolAddress((void**)&mean_fh0, g_mean_fh0);
    cudaGetSymbolAddress((void**)&fm1,      g_featmap1);
    cudaGetSymbolAddress((void**)&fm0,      g_featmap0);
    cudaGetSymbolAddress((void**)&x1v,      g_x1);
    cudaGetSymbolAddress((void**)&out512,   g_out512);
    cudaGetSymbolAddress((void**)&wpad,     g_wpad);

    // 1) pad the four layer-1 weight matrices
    pad_w_kernel<<<dim3((HH * FP + 255) / 256, 4), 256>>>(w1a_self, w1a_neigh, w1b_self, w1b_neigh);
    // 2) hop0 index + hop1 gather + neighbor mean + fh0 materialize
    gather_hop_kernel<<<M1, 256>>>(features, adj, x, perm0, perm1);
    // 3) seed gather + hop0 mean
    gather_seed_kernel<<<BB, 256>>>(features, x);
    // 4) featmap1 raw = [fh0 @ w1b_self^T | neigh1 @ w1b_neigh^T]
    wmma_gemm_dual<<<dim3(256 / BN, M1 / BM, 2), 128>>>(
        fh0,    wpad + (size_t)2 * HH * FP,
        neigh1, wpad + (size_t)3 * HH * FP,
        fm1, M1, FP);
    // 5) featmap0 raw = [selfx @ w1a_self^T | mean_fh0 @ w1a_neigh^T]
    wmma_gemm_dual<<<dim3(256 / BN, BB / BM, 2), 128>>>(
        selfx,    wpad + (size_t)0 * HH * FP,
        mean_fh0, wpad + (size_t)1 * HH * FP,
        fm0, BB, FP);
    //    featmap0 = relu(raw + bias)  (needed as GEMM3 input)
    bias_relu_kernel<<<BB, 512>>>(fm0, b1a_self, b1a_neigh);
    // 6) x1 = mean_s relu(featmap1 + bias)
    reduce_x1_kernel<<<BB, 512>>>(b1b_self, b1b_neigh);
    // 7) out512 raw = [featmap0 @ w2_self^T | x1 @ w2_neigh^T]
    wmma_gemm_dual<<<dim3(256 / BN, BB / BM, 2), 128>>>(
        fm0, w2_self,
        x1v, w2_neigh,
        out512, BB, 512);
    // 8) bias + layernorm + classifier
    ln_cls_kernel<<<BB, 512>>>(b2_self, b2_neigh, ln_g, ln_b, w_cls, b_cls, out);
}